// round 14
// baseline (speedup 1.0000x reference)
#include <cuda_runtime.h>
#include <cuda_bf16.h>
#include <cstdio>

// Problem constants
#define Bz 2
#define Tz 2048
#define Dz 1024
#define Hz 16
#define DHz 64
#define NREL 7

// Scratch (device globals; allocation-free)
__device__ float g_Q[Bz*Tz*Hz*DHz];
__device__ float g_K[Bz*Tz*Hz*DHz];
__device__ float g_V[Bz*Tz*Hz*DHz];
__device__ float g_O[Bz*Tz*Hz*DHz];
__device__ float g_PK[NREL*Hz*DHz];

// ---------------------------------------------------------------------------
// GEMM core: C[M,N] = A[M,K] @ W[K,N] + bias[N]
// BM=BN=128, BK=16, 256 threads, 8x8 per thread. (measured: L1-bound 81.6%,
// fma 52% — unchanged this round)
// ---------------------------------------------------------------------------
__device__ __forceinline__ void sgemm_body(
    const float* __restrict__ A, const float* __restrict__ W,
    const float* __restrict__ bias, float* __restrict__ C,
    int M, int N, int K)
{
    __shared__ float As[2][16][128];
    __shared__ float Ws[2][16][128];

    const int tid = threadIdx.x;
    const int row0 = blockIdx.y * 128;
    const int col0 = blockIdx.x * 128;

    const int a_r = tid >> 1;
    const int a_c = (tid & 1) * 4;
    const int w_r = tid >> 5;
    const int w_c = (tid & 31) * 4;

    const int tx = tid & 15;
    const int ty = tid >> 4;

    float acc[8][8];
    #pragma unroll
    for (int i = 0; i < 8; i++)
        #pragma unroll
        for (int j = 0; j < 8; j++) acc[i][j] = 0.f;

    const float* a_ptr = &A[(size_t)(row0 + a_r) * K + a_c];
    const float* w_ptr = &W[(size_t)w_r * N + col0 + w_c];

    float4 av0 = *(const float4*)a_ptr;
    float4 av1 = *(const float4*)(a_ptr + 8);
    float4 wv0 = *(const float4*)w_ptr;
    float4 wv1 = *(const float4*)(w_ptr + (size_t)8 * N);

    As[0][a_c + 0][a_r] = av0.x;
    As[0][a_c + 1][a_r] = av0.y;
    As[0][a_c + 2][a_r] = av0.z;
    As[0][a_c + 3][a_r] = av0.w;
    As[0][a_c + 8][a_r] = av1.x;
    As[0][a_c + 9][a_r] = av1.y;
    As[0][a_c +10][a_r] = av1.z;
    As[0][a_c +11][a_r] = av1.w;
    *(float4*)&Ws[0][w_r    ][w_c] = wv0;
    *(float4*)&Ws[0][w_r + 8][w_c] = wv1;
    __syncthreads();

    for (int k0 = 0; k0 < K; k0 += 16) {
        const int buf = (k0 >> 4) & 1;
        const bool more = (k0 + 16) < K;

        if (more) {
            av0 = *(const float4*)(a_ptr + k0 + 16);
            av1 = *(const float4*)(a_ptr + k0 + 24);
            wv0 = *(const float4*)(w_ptr + (size_t)(k0 + 16) * N);
            wv1 = *(const float4*)(w_ptr + (size_t)(k0 + 24) * N);
        }

        #pragma unroll
        for (int kk = 0; kk < 16; kk++) {
            float a[8], b[8];
            *(float4*)(a)     = *(float4*)&As[buf][kk][ty * 8];
            *(float4*)(a + 4) = *(float4*)&As[buf][kk][ty * 8 + 4];
            *(float4*)(b)     = *(float4*)&Ws[buf][kk][tx * 8];
            *(float4*)(b + 4) = *(float4*)&Ws[buf][kk][tx * 8 + 4];
            #pragma unroll
            for (int i = 0; i < 8; i++)
                #pragma unroll
                for (int j = 0; j < 8; j++)
                    acc[i][j] += a[i] * b[j];
        }

        if (more) {
            const int nb = buf ^ 1;
            As[nb][a_c + 0][a_r] = av0.x;
            As[nb][a_c + 1][a_r] = av0.y;
            As[nb][a_c + 2][a_r] = av0.z;
            As[nb][a_c + 3][a_r] = av0.w;
            As[nb][a_c + 8][a_r] = av1.x;
            As[nb][a_c + 9][a_r] = av1.y;
            As[nb][a_c +10][a_r] = av1.z;
            As[nb][a_c +11][a_r] = av1.w;
            *(float4*)&Ws[nb][w_r    ][w_c] = wv0;
            *(float4*)&Ws[nb][w_r + 8][w_c] = wv1;
            __syncthreads();
        }
    }

    const float4 bv0 = *(const float4*)&bias[col0 + tx * 8];
    const float4 bv1 = *(const float4*)&bias[col0 + tx * 8 + 4];
    #pragma unroll
    for (int i = 0; i < 8; i++) {
        int row = row0 + ty * 8 + i;
        float4 out0, out1;
        out0.x = acc[i][0] + bv0.x;
        out0.y = acc[i][1] + bv0.y;
        out0.z = acc[i][2] + bv0.z;
        out0.w = acc[i][3] + bv0.w;
        out1.x = acc[i][4] + bv1.x;
        out1.y = acc[i][5] + bv1.y;
        out1.z = acc[i][6] + bv1.z;
        out1.w = acc[i][7] + bv1.w;
        *(float4*)&C[(size_t)row * N + col0 + tx * 8]     = out0;
        *(float4*)&C[(size_t)row * N + col0 + tx * 8 + 4] = out1;
    }
}

__global__ __launch_bounds__(256, 2) void sgemm_bias(
    const float* __restrict__ A, const float* __restrict__ W,
    const float* __restrict__ bias, float* __restrict__ C,
    int M, int N, int K)
{
    sgemm_body(A, W, bias, C, M, N, K);
}

__global__ __launch_bounds__(256, 2) void sgemm_bias_qkv(
    const float* __restrict__ Aq, const float* __restrict__ Ak,
    const float* __restrict__ Av,
    const float* __restrict__ Wq, const float* __restrict__ Wk,
    const float* __restrict__ Wv,
    const float* __restrict__ bq, const float* __restrict__ bk,
    const float* __restrict__ bv,
    float* __restrict__ Cq, float* __restrict__ Ck, float* __restrict__ Cv,
    const float* __restrict__ pos_emb, float* __restrict__ PK,
    int M, int N, int K)
{
    if (blockIdx.z == 3) {
        int id = blockIdx.y * gridDim.x + blockIdx.x;
        if (id >= 4 * NREL) return;
        int r = id / 4;
        int n = (id % 4) * 256 + threadIdx.x;
        float sum = bk[n];
        const float* pe = pos_emb + (size_t)r * Dz;
        #pragma unroll 4
        for (int k = 0; k < Dz; k++)
            sum += pe[k] * Wk[(size_t)k * (Hz*DHz) + n];
        PK[r * (Hz*DHz) + n] = sum;
        return;
    }
    const float* A; const float* W; const float* bias; float* C;
    if (blockIdx.z == 0)      { A = Aq; W = Wq; bias = bq; C = Cq; }
    else if (blockIdx.z == 1) { A = Ak; W = Wk; bias = bk; C = Ck; }
    else                      { A = Av; W = Wv; bias = bv; C = Cv; }
    sgemm_body(A, W, bias, C, M, N, K);
}

// ---------------------------------------------------------------------------
// Flash attention, 128x128 tiles, 512 threads, 1 CTA/SM (16 warps/SM).
// S phase: 8 rows x 4 cols/thread (ty = tid>>5 warp-uniform -> qs reads are
// warp broadcasts; row-group = full warp, 5-step shuffle reductions).
// PV phase: 8 rows x 2 dims/thread with the SAME rows (same ty) -> m/l/corr
// stay in registers, no cross-mapping relay.
// Halves barriers, corr-exp2 and m/l work per unit of attention work vs the
// 64-wide version (16 key tiles instead of 32).
// Smem 174KB total; FSCALE pre-folded into qs/adjs; smalls computed in the
// prologue from qs and pk.
// ---------------------------------------------------------------------------
#define QSTR 132                     // qs minor stride (128 rows + pad)
#define CSTR 132                     // ks/ps minor stride (128 cols + pad)
#define VSTR 68                      // vs minor stride (64 dims + pad)
#define FLASH_SMEM ((64*QSTR + 64*CSTR + 128*VSTR + 128*CSTR + 128*8) * 4)
#define FSCALE 0.18033688011112042f  // (1/sqrt(64)) * log2(e)

__global__ __launch_bounds__(512, 1) void flash_attn(
    const float* __restrict__ Q, const float* __restrict__ Kt,
    const float* __restrict__ V, const float* __restrict__ PK,
    const float* __restrict__ u, const float* __restrict__ rb,
    float* __restrict__ O)
{
    extern __shared__ float sm[];
    float* qs = sm;                   // [64 d][QSTR]  FSCALE*(q+u) transposed
    float* ks = qs + 64 * QSTR;       // [64 d][CSTR]  k transposed [d][c], c<128
    float* vs = ks + 64 * CSTR;       // [128 c][VSTR] v natural    [c][d]
    float* ps = vs + 128 * VSTR;      // [128 r][CSTR] p natural    [r][c]
    float* smalls = ps + 128 * CSTR;  // [128][8]  (pre-scaled by FSCALE)

    const int tid = threadIdx.x;
    const int bh = blockIdx.y;
    const int h = bh & (Hz - 1);
    const int b = bh >> 4;
    const int t0 = blockIdx.x * 128;
    const size_t base = ((size_t)b * Tz) * (Hz*DHz) + h * DHz;

    // q tile (transposed), content bias folded, pre-scaled. 128x16 float4.
    for (int idx = tid; idx < 128 * 16; idx += 512) {
        int r = idx >> 4, d4 = (idx & 15) * 4;
        float4 qv = *(const float4*)&Q[base + (size_t)(t0 + r) * (Hz*DHz) + d4];
        float4 uv = *(const float4*)&u[h * DHz + d4];
        qs[(d4 + 0) * QSTR + r] = (qv.x + uv.x) * FSCALE;
        qs[(d4 + 1) * QSTR + r] = (qv.y + uv.y) * FSCALE;
        qs[(d4 + 2) * QSTR + r] = (qv.z + uv.z) * FSCALE;
        qs[(d4 + 3) * QSTR + r] = (qv.w + uv.w) * FSCALE;
    }
    // stage pk (7x64) and adj = FSCALE*(rb-u) into the ps area (unused yet)
    float* pks  = ps;             // [NREL][64]
    float* adjs = ps + NREL * 64; // [64]
    if (tid < NREL * 64) {
        int j = tid >> 6, d = tid & 63;
        pks[tid] = PK[j * (Hz*DHz) + h * DHz + d];
    }
    if (tid >= 448 && tid < 512)
        adjs[tid - 448] = (rb[h * DHz + (tid - 448)] - u[h * DHz + (tid - 448)]) * FSCALE;
    __syncthreads();

    // smalls[r][j] = sum_d (qs_scaled[d][r] + adj_scaled[d]) * pk[j][d]
    for (int idx = tid; idx < 128 * NREL; idx += 512) {
        int r = idx / NREL, j = idx % NREL;
        float sum = 0.f;
        #pragma unroll 8
        for (int d = 0; d < 64; d++)
            sum += (qs[d * QSTR + r] + adjs[d]) * pks[j * 64 + d];
        smalls[r * 8 + j] = sum;
    }

    const int txs = tid & 31;  // S phase: 4 key-cols (of 128)
    const int ty  = tid >> 5;  // 8 q-rows (warp-uniform)

    float o[8][2];
    float m_i[8], l_i[8];
    #pragma unroll
    for (int i = 0; i < 8; i++) {
        m_i[i] = -1e30f; l_i[i] = 0.f;
        o[i][0] = 0.f; o[i][1] = 0.f;
    }
    __syncthreads();  // smalls visible; pks/adjs area free for P reuse

    for (int kt = 0; kt < Tz; kt += 128) {
        // K (transposed [d][c]) and V (natural [c][d]), LDG.128 each:
        // 128 rows x 16 float4 = 4 iters/thread.
        for (int idx = tid; idx < 128 * 16; idx += 512) {
            int c = idx >> 4, d4 = (idx & 15) * 4;
            size_t g = base + (size_t)(kt + c) * (Hz*DHz) + d4;
            float4 kv = *(const float4*)&Kt[g];
            float4 vv = *(const float4*)&V[g];
            ks[(d4 + 0) * CSTR + c] = kv.x;
            ks[(d4 + 1) * CSTR + c] = kv.y;
            ks[(d4 + 2) * CSTR + c] = kv.z;
            ks[(d4 + 3) * CSTR + c] = kv.w;
            *(float4*)&vs[c * VSTR + d4] = vv;
        }
        __syncthreads();

        // S = qs_scaled . k^T  (8 rows x 4 cols per thread)
        float s[8][4];
        #pragma unroll
        for (int i = 0; i < 8; i++)
            #pragma unroll
            for (int j = 0; j < 4; j++) s[i][j] = 0.f;
        #pragma unroll
        for (int d = 0; d < 64; d++) {
            float a[8], bb[4];
            *(float4*)(a)     = *(float4*)&qs[d * QSTR + 8 * ty];      // bcast
            *(float4*)(a + 4) = *(float4*)&qs[d * QSTR + 8 * ty + 4];  // bcast
            *(float4*)(bb)    = *(float4*)&ks[d * CSTR + 4 * txs];
            #pragma unroll
            for (int i = 0; i < 8; i++)
                #pragma unroll
                for (int j = 0; j < 4; j++)
                    s[i][j] += a[i] * bb[j];
        }

        // relative bias (pre-scaled): bare FADD.
        if (t0 >= kt + 130) {           // all t-T >= 3 -> idx 6
            #pragma unroll
            for (int i = 0; i < 8; i++) {
                float bias = smalls[(8 * ty + i) * 8 + 6];
                #pragma unroll
                for (int j = 0; j < 4; j++) s[i][j] += bias;
            }
        } else if (kt >= t0 + 130) {    // all t-T <= -3 -> idx 0
            #pragma unroll
            for (int i = 0; i < 8; i++) {
                float bias = smalls[(8 * ty + i) * 8 + 0];
                #pragma unroll
                for (int j = 0; j < 4; j++) s[i][j] += bias;
            }
        } else {                        // mixed tile
            #pragma unroll
            for (int i = 0; i < 8; i++) {
                int t_g = t0 + 8 * ty + i;
                #pragma unroll
                for (int j = 0; j < 4; j++) {
                    int T_g = kt + 4 * txs + j;
                    int diff = t_g - T_g;
                    diff = max(-3, min(3, diff));
                    s[i][j] += smalls[(8 * ty + i) * 8 + diff + 3];
                }
            }
        }

        // online softmax (full-warp row groups, 5 shuffle steps)
        #pragma unroll
        for (int i = 0; i < 8; i++) {
            float mt = s[i][0];
            #pragma unroll
            for (int j = 1; j < 4; j++) mt = fmaxf(mt, s[i][j]);
            #pragma unroll
            for (int off = 16; off >= 1; off >>= 1)
                mt = fmaxf(mt, __shfl_xor_sync(0xffffffffu, mt, off));
            float mn = fmaxf(m_i[i], mt);
            float corr = exp2f(m_i[i] - mn);
            m_i[i] = mn;
            l_i[i] *= corr;
            float rs = 0.f;
            #pragma unroll
            for (int j = 0; j < 4; j++) {
                float p = exp2f(s[i][j] - mn);
                s[i][j] = p; rs += p;
            }
            #pragma unroll
            for (int off = 16; off >= 1; off >>= 1)
                rs += __shfl_xor_sync(0xffffffffu, rs, off);
            l_i[i] += rs;
            o[i][0] *= corr;
            o[i][1] *= corr;
        }

        // write P
        #pragma unroll
        for (int i = 0; i < 8; i++) {
            float4 pv = make_float4(s[i][0], s[i][1], s[i][2], s[i][3]);
            *(float4*)&ps[(8 * ty + i) * CSTR + 4 * txs] = pv;
        }
        __syncthreads();

        // O += P @ V  (8 rows x 2 dims per thread; same rows as S phase)
        const int txv = tid & 15;  // hmm: need 32 lanes for dims? no: 2*txs
        (void)txv;
        #pragma unroll
        for (int c0 = 0; c0 < 128; c0 += 4) {
            float4 a4[8];
            #pragma unroll
            for (int i = 0; i < 8; i++)
                a4[i] = *(const float4*)&ps[(8 * ty + i) * CSTR + c0];  // bcast
            #pragma unroll
            for (int j4 = 0; j4 < 4; j4++) {
                float2 bf = *(const float2*)&vs[(c0 + j4) * VSTR + 2 * txs];
                float aj;
                #pragma unroll
                for (int i = 0; i < 8; i++) {
                    aj = (j4 == 0) ? a4[i].x : (j4 == 1) ? a4[i].y
                       : (j4 == 2) ? a4[i].z : a4[i].w;
                    o[i][0] += aj * bf.x;
                    o[i][1] += aj * bf.y;
                }
            }
        }
        __syncthreads();
    }

    // normalize + store (dims 2*txs, rows 8*ty+i)
    #pragma unroll
    for (int i = 0; i < 8; i++) {
        float inv = 1.f / l_i[i];
        int t_g = t0 + 8 * ty + i;
        float2 ov = make_float2(o[i][0] * inv, o[i][1] * inv);
        *(float2*)&O[base + (size_t)t_g * (Hz*DHz) + 2 * txs] = ov;
    }
}

// ---------------------------------------------------------------------------
extern "C" void kernel_launch(void* const* d_in, const int* in_sizes, int n_in,
                              void* d_out, int out_size)
{
    const float* query = (const float*)d_in[0];
    const float* key   = (const float*)d_in[1];
    const float* value = (const float*)d_in[2];
    const float* Wq    = (const float*)d_in[3];
    const float* bq    = (const float*)d_in[4];
    const float* Wk    = (const float*)d_in[5];
    const float* bk    = (const float*)d_in[6];
    const float* Wv    = (const float*)d_in[7];
    const float* bv    = (const float*)d_in[8];
    const float* Wo    = (const float*)d_in[9];
    const float* bo    = (const float*)d_in[10];
    const float* cb    = (const float*)d_in[11];
    const float* rb    = (const float*)d_in[12];
    const float* pe    = (const float*)d_in[13];
    float* out = (float*)d_out;

    float *pQ, *pK, *pV, *pO, *pPK;
    cudaGetSymbolAddress((void**)&pQ, g_Q);
    cudaGetSymbolAddress((void**)&pK, g_K);
    cudaGetSymbolAddress((void**)&pV, g_V);
    cudaGetSymbolAddress((void**)&pO, g_O);
    cudaGetSymbolAddress((void**)&pPK, g_PK);

    static bool attr_set = false;
    if (!attr_set) {
        cudaFuncSetAttribute(flash_attn,
                             cudaFuncAttributeMaxDynamicSharedMemorySize,
                             FLASH_SMEM);
        attr_set = true;
    }

    const int M = Bz * Tz;        // 4096
    const int N = Hz * DHz;       // 1024
    const int K = Dz;             // 1024

    dim3 qkv_grid(N / 128, M / 128, 4);  // z: QKV GEMMs + pk layer
    sgemm_bias_qkv<<<qkv_grid, 256>>>(
        query, key, value, Wq, Wk, Wv, bq, bk, bv, pQ, pK, pV,
        pe, pPK, M, N, K);

    // flash attention: 128x128 tiles, 512 threads
    flash_attn<<<dim3(Tz / 128, Bz * Hz), 512, FLASH_SMEM>>>(
        pQ, pK, pV, pPK, cb, rb, pO);

    dim3 gemm_grid(Dz / 128, M / 128);
    sgemm_bias<<<gemm_grid, 256>>>(pO, Wo, bo, out, M, Dz, N);
}

// round 17
// speedup vs baseline: 1.1523x; 1.1523x over previous
#include <cuda_runtime.h>
#include <cuda_bf16.h>
#include <cstdio>

// Problem constants
#define Bz 2
#define Tz 2048
#define Dz 1024
#define Hz 16
#define DHz 64
#define NREL 7

// Scratch (device globals; allocation-free)
__device__ float g_Q[Bz*Tz*Hz*DHz];
__device__ float g_K[Bz*Tz*Hz*DHz];
__device__ float g_V[Bz*Tz*Hz*DHz];
__device__ float g_O[Bz*Tz*Hz*DHz];
__device__ float g_PK[NREL*Hz*DHz];

// ---------------------------------------------------------------------------
// GEMM core: C[M,N] = A[M,K] @ W[K,N] + bias[N]
// BM=BN=128, BK=16, 256 threads, 8x8 per thread.
// Column mapping per thread: {4tx..4tx+3, 64+4tx..64+4tx+3} — the 16
// distinct b-float4s per warp are contiguous 256B -> conflict-free 2-phase
// LDS (was 4-way conflicted at the old {8tx} mapping; measured L1=81.6%
// vs fma=52% pointed here).
// ---------------------------------------------------------------------------
__device__ __forceinline__ void sgemm_body(
    const float* __restrict__ A, const float* __restrict__ W,
    const float* __restrict__ bias, float* __restrict__ C,
    int M, int N, int K)
{
    __shared__ float As[2][16][128];
    __shared__ float Ws[2][16][128];

    const int tid = threadIdx.x;
    const int row0 = blockIdx.y * 128;
    const int col0 = blockIdx.x * 128;

    const int a_r = tid >> 1;
    const int a_c = (tid & 1) * 4;
    const int w_r = tid >> 5;
    const int w_c = (tid & 31) * 4;

    const int tx = tid & 15;
    const int ty = tid >> 4;

    float acc[8][8];
    #pragma unroll
    for (int i = 0; i < 8; i++)
        #pragma unroll
        for (int j = 0; j < 8; j++) acc[i][j] = 0.f;

    const float* a_ptr = &A[(size_t)(row0 + a_r) * K + a_c];
    const float* w_ptr = &W[(size_t)w_r * N + col0 + w_c];

    float4 av0 = *(const float4*)a_ptr;
    float4 av1 = *(const float4*)(a_ptr + 8);
    float4 wv0 = *(const float4*)w_ptr;
    float4 wv1 = *(const float4*)(w_ptr + (size_t)8 * N);

    As[0][a_c + 0][a_r] = av0.x;
    As[0][a_c + 1][a_r] = av0.y;
    As[0][a_c + 2][a_r] = av0.z;
    As[0][a_c + 3][a_r] = av0.w;
    As[0][a_c + 8][a_r] = av1.x;
    As[0][a_c + 9][a_r] = av1.y;
    As[0][a_c +10][a_r] = av1.z;
    As[0][a_c +11][a_r] = av1.w;
    *(float4*)&Ws[0][w_r    ][w_c] = wv0;
    *(float4*)&Ws[0][w_r + 8][w_c] = wv1;
    __syncthreads();

    for (int k0 = 0; k0 < K; k0 += 16) {
        const int buf = (k0 >> 4) & 1;
        const bool more = (k0 + 16) < K;

        if (more) {
            av0 = *(const float4*)(a_ptr + k0 + 16);
            av1 = *(const float4*)(a_ptr + k0 + 24);
            wv0 = *(const float4*)(w_ptr + (size_t)(k0 + 16) * N);
            wv1 = *(const float4*)(w_ptr + (size_t)(k0 + 24) * N);
        }

        #pragma unroll
        for (int kk = 0; kk < 16; kk++) {
            float a[8], b[8];
            *(float4*)(a)     = *(float4*)&As[buf][kk][ty * 8];
            *(float4*)(a + 4) = *(float4*)&As[buf][kk][ty * 8 + 4];
            *(float4*)(b)     = *(float4*)&Ws[buf][kk][tx * 4];        // cols 4tx..+3
            *(float4*)(b + 4) = *(float4*)&Ws[buf][kk][64 + tx * 4];   // cols 64+4tx..+3
            #pragma unroll
            for (int i = 0; i < 8; i++)
                #pragma unroll
                for (int j = 0; j < 8; j++)
                    acc[i][j] += a[i] * b[j];
        }

        if (more) {
            const int nb = buf ^ 1;
            As[nb][a_c + 0][a_r] = av0.x;
            As[nb][a_c + 1][a_r] = av0.y;
            As[nb][a_c + 2][a_r] = av0.z;
            As[nb][a_c + 3][a_r] = av0.w;
            As[nb][a_c + 8][a_r] = av1.x;
            As[nb][a_c + 9][a_r] = av1.y;
            As[nb][a_c +10][a_r] = av1.z;
            As[nb][a_c +11][a_r] = av1.w;
            *(float4*)&Ws[nb][w_r    ][w_c] = wv0;
            *(float4*)&Ws[nb][w_r + 8][w_c] = wv1;
            __syncthreads();
        }
    }

    // epilogue: columns 4tx (j 0-3) and 64+4tx (j 4-7)
    const float4 bv0 = *(const float4*)&bias[col0 + tx * 4];
    const float4 bv1 = *(const float4*)&bias[col0 + 64 + tx * 4];
    #pragma unroll
    for (int i = 0; i < 8; i++) {
        int row = row0 + ty * 8 + i;
        float4 out0, out1;
        out0.x = acc[i][0] + bv0.x;
        out0.y = acc[i][1] + bv0.y;
        out0.z = acc[i][2] + bv0.z;
        out0.w = acc[i][3] + bv0.w;
        out1.x = acc[i][4] + bv1.x;
        out1.y = acc[i][5] + bv1.y;
        out1.z = acc[i][6] + bv1.z;
        out1.w = acc[i][7] + bv1.w;
        *(float4*)&C[(size_t)row * N + col0 + tx * 4]      = out0;
        *(float4*)&C[(size_t)row * N + col0 + 64 + tx * 4] = out1;
    }
}

__global__ __launch_bounds__(256, 2) void sgemm_bias(
    const float* __restrict__ A, const float* __restrict__ W,
    const float* __restrict__ bias, float* __restrict__ C,
    int M, int N, int K)
{
    sgemm_body(A, W, bias, C, M, N, K);
}

__global__ __launch_bounds__(256, 2) void sgemm_bias_qkv(
    const float* __restrict__ Aq, const float* __restrict__ Ak,
    const float* __restrict__ Av,
    const float* __restrict__ Wq, const float* __restrict__ Wk,
    const float* __restrict__ Wv,
    const float* __restrict__ bq, const float* __restrict__ bk,
    const float* __restrict__ bv,
    float* __restrict__ Cq, float* __restrict__ Ck, float* __restrict__ Cv,
    const float* __restrict__ pos_emb, float* __restrict__ PK,
    int M, int N, int K)
{
    if (blockIdx.z == 3) {
        int id = blockIdx.y * gridDim.x + blockIdx.x;
        if (id >= 4 * NREL) return;
        int r = id / 4;
        int n = (id % 4) * 256 + threadIdx.x;
        float sum = bk[n];
        const float* pe = pos_emb + (size_t)r * Dz;
        #pragma unroll 4
        for (int k = 0; k < Dz; k++)
            sum += pe[k] * Wk[(size_t)k * (Hz*DHz) + n];
        PK[r * (Hz*DHz) + n] = sum;
        return;
    }
    const float* A; const float* W; const float* bias; float* C;
    if (blockIdx.z == 0)      { A = Aq; W = Wq; bias = bq; C = Cq; }
    else if (blockIdx.z == 1) { A = Ak; W = Wk; bias = bk; C = Ck; }
    else                      { A = Av; W = Wv; bias = bv; C = Cv; }
    sgemm_body(A, W, bias, C, M, N, K);
}

// ---------------------------------------------------------------------------
// Flash attention — measured-best R13 configuration (128x64 tiles, 256 thr,
// 2 CTAs/SM) + XOR-swizzled ks columns: logical (d,c) lives at physical
// column c ^ (((d>>2)&7)<<2). Fixes the 8-way STS conflict in the K
// transpose store (addr stride 4*KSTR ≡ 16 mod 32 gave 2 banks for 16
// lanes). Reads fold the swizzle at compile time (S-loop fully unrolled).
// ---------------------------------------------------------------------------
#define QSTR 132                     // stride for qs rows (128 q-rows + pad)
#define KSTR 68                      // stride for ks/vs/ps minor dim (64 + pad)
#define FLASH_SMEM ((64 * QSTR + 2 * 64 * KSTR + 128 * KSTR + 128 * 8) * 4)
#define FSCALE 0.18033688011112042f  // (1/sqrt(64)) * log2(e)
#define KSWZ(d) ((((d) >> 2) & 7) << 2)

__global__ __launch_bounds__(256, 2) void flash_attn(
    const float* __restrict__ Q, const float* __restrict__ Kt,
    const float* __restrict__ V, const float* __restrict__ PK,
    const float* __restrict__ u, const float* __restrict__ rb,
    float* __restrict__ O)
{
    extern __shared__ float sm[];
    float* qs = sm;                   // [64 d][QSTR]  FSCALE*(q+u) transposed
    float* ks = qs + 64 * QSTR;       // [64 d][KSTR]  k transposed, col-swizzled
    float* vs = ks + 64 * KSTR;       // [64 c][KSTR]  v natural    [c][d]
    float* ps = vs + 64 * KSTR;       // [128 r][KSTR] p natural    [r][c]
    float* smalls = ps + 128 * KSTR;  // [128][8]  (pre-scaled by FSCALE)

    const int tid = threadIdx.x;
    const int bh = blockIdx.y;
    const int h = bh & (Hz - 1);
    const int b = bh >> 4;
    const int t0 = blockIdx.x * 128;
    const size_t base = ((size_t)b * Tz) * (Hz*DHz) + h * DHz;

    for (int idx = tid; idx < 128 * 16; idx += 256) {
        int r = idx >> 4, d4 = (idx & 15) * 4;
        float4 qv = *(const float4*)&Q[base + (size_t)(t0 + r) * (Hz*DHz) + d4];
        float4 uv = *(const float4*)&u[h * DHz + d4];
        qs[(d4 + 0) * QSTR + r] = (qv.x + uv.x) * FSCALE;
        qs[(d4 + 1) * QSTR + r] = (qv.y + uv.y) * FSCALE;
        qs[(d4 + 2) * QSTR + r] = (qv.z + uv.z) * FSCALE;
        qs[(d4 + 3) * QSTR + r] = (qv.w + uv.w) * FSCALE;
    }
    float* pks  = ps;             // [NREL][64]
    float* adjs = ps + NREL * 64; // [64]
    for (int idx = tid; idx < NREL * 64; idx += 256) {
        int j = idx >> 6, d = idx & 63;
        pks[idx] = PK[j * (Hz*DHz) + h * DHz + d];
    }
    if (tid < 64)
        adjs[tid] = (rb[h * DHz + tid] - u[h * DHz + tid]) * FSCALE;
    __syncthreads();

    for (int idx = tid; idx < 128 * NREL; idx += 256) {
        int r = idx / NREL, j = idx % NREL;
        float sum = 0.f;
        #pragma unroll 8
        for (int d = 0; d < 64; d++)
            sum += (qs[d * QSTR + r] + adjs[d]) * pks[j * 64 + d];
        smalls[r * 8 + j] = sum;
    }

    const int tx = tid & 15;
    const int ty = tid >> 4;

    float o[8][4];
    float m_i[8], l_i[8];
    #pragma unroll
    for (int i = 0; i < 8; i++) {
        m_i[i] = -1e30f; l_i[i] = 0.f;
        #pragma unroll
        for (int j = 0; j < 4; j++) o[i][j] = 0.f;
    }
    __syncthreads();

    for (int kt = 0; kt < Tz; kt += 64) {
        for (int idx = tid; idx < 64 * 16; idx += 256) {
            int c = idx >> 4, d4 = (idx & 15) * 4;
            size_t g = base + (size_t)(kt + c) * (Hz*DHz) + d4;
            float4 kv = *(const float4*)&Kt[g];
            float4 vv = *(const float4*)&V[g];
            int cs = c ^ KSWZ(d4);   // same swizzle for d4..d4+3 (d>>2 equal)
            ks[(d4 + 0) * KSTR + cs] = kv.x;
            ks[(d4 + 1) * KSTR + cs] = kv.y;
            ks[(d4 + 2) * KSTR + cs] = kv.z;
            ks[(d4 + 3) * KSTR + cs] = kv.w;
            *(float4*)&vs[c * KSTR + d4] = vv;
        }
        __syncthreads();

        float s[8][4];
        #pragma unroll
        for (int i = 0; i < 8; i++)
            #pragma unroll
            for (int j = 0; j < 4; j++) s[i][j] = 0.f;
        #pragma unroll
        for (int d = 0; d < 64; d++) {
            float a[8], bb[4];
            *(float4*)(a)     = *(float4*)&qs[d * QSTR + 8 * ty];
            *(float4*)(a + 4) = *(float4*)&qs[d * QSTR + 8 * ty + 4];
            // swizzle folds to an immediate: d is a compile-time constant here
            *(float4*)(bb)    = *(float4*)&ks[d * KSTR + ((4 * tx) ^ KSWZ(d))];
            #pragma unroll
            for (int i = 0; i < 8; i++)
                #pragma unroll
                for (int j = 0; j < 4; j++)
                    s[i][j] += a[i] * bb[j];
        }

        if (t0 >= kt + 66) {
            #pragma unroll
            for (int i = 0; i < 8; i++) {
                float bias = smalls[(8 * ty + i) * 8 + 6];
                #pragma unroll
                for (int j = 0; j < 4; j++) s[i][j] += bias;
            }
        } else if (kt >= t0 + 130) {
            #pragma unroll
            for (int i = 0; i < 8; i++) {
                float bias = smalls[(8 * ty + i) * 8 + 0];
                #pragma unroll
                for (int j = 0; j < 4; j++) s[i][j] += bias;
            }
        } else {
            #pragma unroll
            for (int i = 0; i < 8; i++) {
                int t_g = t0 + 8 * ty + i;
                #pragma unroll
                for (int j = 0; j < 4; j++) {
                    int T_g = kt + 4 * tx + j;
                    int diff = t_g - T_g;
                    diff = max(-3, min(3, diff));
                    s[i][j] += smalls[(8 * ty + i) * 8 + diff + 3];
                }
            }
        }

        #pragma unroll
        for (int i = 0; i < 8; i++) {
            float mt = s[i][0];
            #pragma unroll
            for (int j = 1; j < 4; j++) mt = fmaxf(mt, s[i][j]);
            #pragma unroll
            for (int off = 8; off >= 1; off >>= 1)
                mt = fmaxf(mt, __shfl_xor_sync(0xffffffffu, mt, off));
            float mn = fmaxf(m_i[i], mt);
            float corr = exp2f(m_i[i] - mn);
            m_i[i] = mn;
            l_i[i] *= corr;
            float rs = 0.f;
            #pragma unroll
            for (int j = 0; j < 4; j++) {
                float p = exp2f(s[i][j] - mn);
                s[i][j] = p; rs += p;
            }
            #pragma unroll
            for (int off = 8; off >= 1; off >>= 1)
                rs += __shfl_xor_sync(0xffffffffu, rs, off);
            l_i[i] += rs;
            #pragma unroll
            for (int j = 0; j < 4; j++) o[i][j] *= corr;
        }

        #pragma unroll
        for (int i = 0; i < 8; i++) {
            float4 pv = make_float4(s[i][0], s[i][1], s[i][2], s[i][3]);
            *(float4*)&ps[(8 * ty + i) * KSTR + 4 * tx] = pv;
        }
        __syncthreads();

        #pragma unroll
        for (int c0 = 0; c0 < 64; c0 += 4) {
            float4 a4[8];
            #pragma unroll
            for (int i = 0; i < 8; i++)
                a4[i] = *(const float4*)&ps[(8 * ty + i) * KSTR + c0];
            #pragma unroll
            for (int j4 = 0; j4 < 4; j4++) {
                float4 bf = *(const float4*)&vs[(c0 + j4) * KSTR + 4 * tx];
                float bb[4] = {bf.x, bf.y, bf.z, bf.w};
                float aj;
                #pragma unroll
                for (int i = 0; i < 8; i++) {
                    aj = (j4 == 0) ? a4[i].x : (j4 == 1) ? a4[i].y
                       : (j4 == 2) ? a4[i].z : a4[i].w;
                    #pragma unroll
                    for (int j = 0; j < 4; j++)
                        o[i][j] += aj * bb[j];
                }
            }
        }
        __syncthreads();
    }

    #pragma unroll
    for (int i = 0; i < 8; i++) {
        float inv = 1.f / l_i[i];
        int t_g = t0 + 8 * ty + i;
        float4 ov = make_float4(o[i][0] * inv, o[i][1] * inv,
                                o[i][2] * inv, o[i][3] * inv);
        *(float4*)&O[base + (size_t)t_g * (Hz*DHz) + 4 * tx] = ov;
    }
}

// ---------------------------------------------------------------------------
extern "C" void kernel_launch(void* const* d_in, const int* in_sizes, int n_in,
                              void* d_out, int out_size)
{
    const float* query = (const float*)d_in[0];
    const float* key   = (const float*)d_in[1];
    const float* value = (const float*)d_in[2];
    const float* Wq    = (const float*)d_in[3];
    const float* bq    = (const float*)d_in[4];
    const float* Wk    = (const float*)d_in[5];
    const float* bk    = (const float*)d_in[6];
    const float* Wv    = (const float*)d_in[7];
    const float* bv    = (const float*)d_in[8];
    const float* Wo    = (const float*)d_in[9];
    const float* bo    = (const float*)d_in[10];
    const float* cb    = (const float*)d_in[11];
    const float* rb    = (const float*)d_in[12];
    const float* pe    = (const float*)d_in[13];
    float* out = (float*)d_out;

    float *pQ, *pK, *pV, *pO, *pPK;
    cudaGetSymbolAddress((void**)&pQ, g_Q);
    cudaGetSymbolAddress((void**)&pK, g_K);
    cudaGetSymbolAddress((void**)&pV, g_V);
    cudaGetSymbolAddress((void**)&pO, g_O);
    cudaGetSymbolAddress((void**)&pPK, g_PK);

    static bool attr_set = false;
    if (!attr_set) {
        cudaFuncSetAttribute(flash_attn,
                             cudaFuncAttributeMaxDynamicSharedMemorySize,
                             FLASH_SMEM);
        attr_set = true;
    }

    const int M = Bz * Tz;        // 4096
    const int N = Hz * DHz;       // 1024
    const int K = Dz;             // 1024

    dim3 qkv_grid(N / 128, M / 128, 4);  // z: QKV GEMMs + pk layer
    sgemm_bias_qkv<<<qkv_grid, 256>>>(
        query, key, value, Wq, Wk, Wv, bq, bk, bv, pQ, pK, pV,
        pe, pPK, M, N, K);

    // flash attention: 128x64 tiles, 256 threads (measured-best config)
    flash_attn<<<dim3(Tz / 128, Bz * Hz), 256, FLASH_SMEM>>>(
        pQ, pK, pV, pPK, cb, rb, pO);

    dim3 gemm_grid(Dz / 128, M / 128);
    sgemm_bias<<<gemm_grid, 256>>>(pO, Wo, bo, out, M, Dz, N);
}